// round 4
// baseline (speedup 1.0000x reference)
#include <cuda_runtime.h>
#include <cfloat>

#define BATCH 4
#define M 4096
#define TX 128
#define NW (TX / 32)          // 4 warps
#define R 4                   // x-points per thread
#define XPB (TX * R)          // 512 x per block
#define XT (M / XPB)          // 8 x-tiles
#define YC 8                  // y-chunks
#define YCHUNK (M / YC)       // 512 y per chunk
#define NBLK (BATCH * XT * YC)  // 256 blocks

// partial mins of squared distance
__device__ float g_row[BATCH * YC * M];  // [b][yc][x]  min over y-chunk
__device__ float g_col[BATCH * XT * M];  // [b][xt][y]  min over x-tile

__global__ __launch_bounds__(TX) void chamfer_main(const float* __restrict__ x,
                                                   const float* __restrict__ y) {
    __shared__ float4 sy[YCHUNK];        // y chunk: (px,py,pz,|p|^2)
    __shared__ float scol[NW][YCHUNK];   // per-warp col-min partials

    int bid = blockIdx.x;
    int yc = bid & (YC - 1);
    int xt = (bid >> 3) & (XT - 1);
    int b  = bid >> 6;

    int tid = threadIdx.x;
    int lane = tid & 31;
    int w = tid >> 5;

    // cooperative load of the y chunk, precomputing |p|^2
    const float* ysrc = y + ((size_t)b * M + yc * YCHUNK) * 3;
    for (int j = tid; j < YCHUNK; j += TX) {
        float p0 = ysrc[j * 3 + 0];
        float p1 = ysrc[j * 3 + 1];
        float p2 = ysrc[j * 3 + 2];
        sy[j] = make_float4(p0, p1, p2, fmaf(p0, p0, fmaf(p1, p1, p2 * p2)));
    }
    for (int i = tid; i < NW * YCHUNK; i += TX) ((float*)scol)[i] = FLT_MAX;

    // my R x-points -> registers
    float n0[R], n1[R], n2[R], sx[R], rmin[R];
    const float* xsrc = x + ((size_t)b * M + xt * XPB) * 3;
#pragma unroll
    for (int r = 0; r < R; r++) {
        int xi = tid + r * TX;
        float a0 = xsrc[xi * 3 + 0];
        float a1 = xsrc[xi * 3 + 1];
        float a2 = xsrc[xi * 3 + 2];
        sx[r] = fmaf(a0, a0, fmaf(a1, a1, a2 * a2));
        n0[r] = -2.0f * a0;
        n1[r] = -2.0f * a1;
        n2[r] = -2.0f * a2;
        rmin[r] = FLT_MAX;
    }
    __syncthreads();

    // volatile pins the LDS/STS order so the cross-lane RMW on scol is safe:
    // lane-staggered j means distinct addresses within each step; a given
    // address is revisited only on the next step, after the store has issued.
    volatile float* sc = scol[w];

#pragma unroll 4
    for (int k = 0; k < YCHUNK; k++) {
        int j = (k + lane) & (YCHUNK - 1);
        float4 p = sy[j];
        float d0 = sx[0] + fmaf(n0[0], p.x, fmaf(n1[0], p.y, fmaf(n2[0], p.z, p.w)));
        float d1 = sx[1] + fmaf(n0[1], p.x, fmaf(n1[1], p.y, fmaf(n2[1], p.z, p.w)));
        float d2 = sx[2] + fmaf(n0[2], p.x, fmaf(n1[2], p.y, fmaf(n2[2], p.z, p.w)));
        float d3 = sx[3] + fmaf(n0[3], p.x, fmaf(n1[3], p.y, fmaf(n2[3], p.z, p.w)));
        rmin[0] = fminf(rmin[0], d0);
        rmin[1] = fminf(rmin[1], d1);
        rmin[2] = fminf(rmin[2], d2);
        rmin[3] = fminf(rmin[3], d3);
        float c = fminf(fminf(d0, d1), fminf(d2, d3));
        sc[j] = fminf(sc[j], c);
    }

    // row-min partials (per x, min over this y-chunk)
#pragma unroll
    for (int r = 0; r < R; r++)
        g_row[((size_t)b * YC + yc) * M + xt * XPB + tid + r * TX] = rmin[r];

    __syncthreads();

    // merge per-warp col-mins, write col partials (per y, min over this x-tile)
    for (int i = tid; i < YCHUNK; i += TX) {
        float v = fminf(fminf(scol[0][i], scol[1][i]),
                        fminf(scol[2][i], scol[3][i]));
        g_col[((size_t)b * XT + xt) * M + yc * YCHUNK + i] = v;
    }
}

__global__ __launch_bounds__(256) void chamfer_final(float* __restrict__ out) {
    int b = blockIdx.x;
    int tid = threadIdx.x;
    float sum = 0.0f;

    // rows: min over YC chunks, then sqrt
    for (int xi = tid; xi < M; xi += 256) {
        const float* p = g_row + (size_t)b * YC * M + xi;
        float v = p[0];
#pragma unroll
        for (int c = 1; c < YC; c++) v = fminf(v, p[(size_t)c * M]);
        sum += sqrtf(fmaxf(v, 0.0f));
    }
    // cols: min over XT tiles, then sqrt
    for (int yi = tid; yi < M; yi += 256) {
        const float* p = g_col + (size_t)b * XT * M + yi;
        float v = p[0];
#pragma unroll
        for (int c = 1; c < XT; c++) v = fminf(v, p[(size_t)c * M]);
        sum += sqrtf(fmaxf(v, 0.0f));
    }

    // block reduction
    __shared__ float red[8];
    for (int o = 16; o; o >>= 1) sum += __shfl_down_sync(0xffffffffu, sum, o);
    if ((tid & 31) == 0) red[tid >> 5] = sum;
    __syncthreads();
    if (tid < 32) {
        float s = (tid < 8) ? red[tid] : 0.0f;
        for (int o = 4; o; o >>= 1) s += __shfl_down_sync(0xffffffffu, s, o);
        if (tid == 0) out[b] = s * (1.0f / (float)M);
    }
}

extern "C" void kernel_launch(void* const* d_in, const int* in_sizes, int n_in,
                              void* d_out, int out_size) {
    const float* x = (const float*)d_in[0];
    const float* y = (const float*)d_in[1];
    float* out = (float*)d_out;

    chamfer_main<<<NBLK, TX>>>(x, y);
    chamfer_final<<<BATCH, 256>>>(out);
}

// round 5
// speedup vs baseline: 1.3411x; 1.3411x over previous
#include <cuda_runtime.h>
#include <cfloat>

#define BATCH 4
#define M 4096
#define TX 128
#define NW (TX / 32)            // 4 warps
#define R 2                     // x-points per thread
#define XPB (TX * R)            // 256 x per block
#define XT (M / XPB)            // 16 x-tiles
#define YC 16                   // y-chunks
#define YCHUNK (M / YC)         // 256 y per chunk
#define NBLK (BATCH * XT * YC)  // 1024 blocks

// partial mins of squared distance
__device__ float g_row[BATCH * YC * M];  // [b][yc][x]  min over y-chunk
__device__ float g_col[BATCH * XT * M];  // [b][xt][y]  min over x-tile
__device__ float g_sums[BATCH * 16];     // per-reduce-block partial sums

__global__ __launch_bounds__(TX) void chamfer_main(const float* __restrict__ x,
                                                   const float* __restrict__ y) {
    __shared__ float4 sy[YCHUNK];        // y chunk: (px,py,pz,|p|^2)
    __shared__ float scol[NW][YCHUNK];   // per-warp col-min partials

    int bid = blockIdx.x;
    int yc = bid & (YC - 1);
    int xt = (bid >> 4) & (XT - 1);
    int b  = bid >> 8;

    int tid = threadIdx.x;
    int lane = tid & 31;
    int w = tid >> 5;

    // cooperative load of the y chunk, precomputing |p|^2
    const float* ysrc = y + ((size_t)b * M + yc * YCHUNK) * 3;
    for (int j = tid; j < YCHUNK; j += TX) {
        float p0 = ysrc[j * 3 + 0];
        float p1 = ysrc[j * 3 + 1];
        float p2 = ysrc[j * 3 + 2];
        sy[j] = make_float4(p0, p1, p2, fmaf(p0, p0, fmaf(p1, p1, p2 * p2)));
    }
    for (int i = tid; i < NW * YCHUNK; i += TX) ((float*)scol)[i] = FLT_MAX;

    // my R x-points -> registers
    float n0[R], n1[R], n2[R], sx[R], rmin[R];
    const float* xsrc = x + ((size_t)b * M + xt * XPB) * 3;
#pragma unroll
    for (int r = 0; r < R; r++) {
        int xi = tid + r * TX;
        float a0 = xsrc[xi * 3 + 0];
        float a1 = xsrc[xi * 3 + 1];
        float a2 = xsrc[xi * 3 + 2];
        sx[r] = fmaf(a0, a0, fmaf(a1, a1, a2 * a2));
        n0[r] = -2.0f * a0;
        n1[r] = -2.0f * a1;
        n2[r] = -2.0f * a2;
        rmin[r] = FLT_MAX;
    }
    __syncthreads();

    // volatile pins LDS/STS order so the cross-lane RMW on scol is safe:
    // lane-staggered j gives distinct addresses within each step; an address
    // is revisited one step later, after the prior STS (same warp, in order).
    volatile float* sc = scol[w];

#pragma unroll 4
    for (int k = 0; k < YCHUNK; k++) {
        int j = (k + lane) & (YCHUNK - 1);
        float4 p = sy[j];
        float d0 = sx[0] + fmaf(n0[0], p.x, fmaf(n1[0], p.y, fmaf(n2[0], p.z, p.w)));
        float d1 = sx[1] + fmaf(n0[1], p.x, fmaf(n1[1], p.y, fmaf(n2[1], p.z, p.w)));
        rmin[0] = fminf(rmin[0], d0);
        rmin[1] = fminf(rmin[1], d1);
        float c = fminf(d0, d1);
        sc[j] = fminf(sc[j], c);
    }

    // row-min partials (per x, min over this y-chunk)
#pragma unroll
    for (int r = 0; r < R; r++)
        g_row[((size_t)b * YC + yc) * M + xt * XPB + tid + r * TX] = rmin[r];

    __syncthreads();

    // merge per-warp col-mins, write col partials (per y, min over this x-tile)
    for (int i = tid; i < YCHUNK; i += TX) {
        float v = fminf(fminf(scol[0][i], scol[1][i]),
                        fminf(scol[2][i], scol[3][i]));
        g_col[((size_t)b * XT + xt) * M + yc * YCHUNK + i] = v;
    }
}

// 64 blocks: [b][seg]; seg 0-7 reduce rows (x), seg 8-15 reduce cols (y).
__global__ __launch_bounds__(256) void chamfer_reduce() {
    int seg = blockIdx.x & 15;
    int b   = blockIdx.x >> 4;
    int tid = threadIdx.x;
    float sum = 0.0f;

    const float* base = (seg < 8) ? (g_row + (size_t)b * YC * M)
                                  : (g_col + (size_t)b * XT * M);
    int off = (seg & 7) * 512;

#pragma unroll
    for (int r = 0; r < 2; r++) {
        const float* p = base + off + r * 256 + tid;
        float v = p[0];
#pragma unroll
        for (int c = 1; c < 16; c++) v = fminf(v, p[(size_t)c * M]);
        sum += sqrtf(fmaxf(v, 0.0f));
    }

    __shared__ float red[8];
    for (int o = 16; o; o >>= 1) sum += __shfl_down_sync(0xffffffffu, sum, o);
    if ((tid & 31) == 0) red[tid >> 5] = sum;
    __syncthreads();
    if (tid < 32) {
        float s = (tid < 8) ? red[tid] : 0.0f;
        for (int o = 4; o; o >>= 1) s += __shfl_down_sync(0xffffffffu, s, o);
        if (tid == 0) g_sums[blockIdx.x] = s;
    }
}

__global__ void chamfer_final(float* __restrict__ out) {
    int t = threadIdx.x;       // 128 threads; warp w handles batch w
    int w = t >> 5, lane = t & 31;
    float v = (lane < 16) ? g_sums[w * 16 + lane] : 0.0f;
    for (int o = 8; o; o >>= 1) v += __shfl_down_sync(0xffffffffu, v, o);
    if (lane == 0) out[w] = v * (1.0f / (float)M);
}

extern "C" void kernel_launch(void* const* d_in, const int* in_sizes, int n_in,
                              void* d_out, int out_size) {
    const float* x = (const float*)d_in[0];
    const float* y = (const float*)d_in[1];
    float* out = (float*)d_out;

    chamfer_main<<<NBLK, TX>>>(x, y);
    chamfer_reduce<<<BATCH * 16, 256>>>();
    chamfer_final<<<1, 128>>>(out);
}

// round 7
// speedup vs baseline: 1.4795x; 1.1032x over previous
#include <cuda_runtime.h>
#include <cfloat>

#define BATCH 4
#define M 4096
#define TX 128
#define NW (TX / 32)            // 4 warps
#define R 4                     // x-points per thread
#define XPB (TX * R)            // 512 x per block
#define XT (M / XPB)            // 8 x-tiles
#define YC 32                   // y-chunks
#define YCHUNK (M / YC)         // 128 y per chunk
#define NBLK (BATCH * XT * YC)  // 1024 blocks
#define NRED 64                 // reduce blocks

// partial mins of squared distance
__device__ float g_row[BATCH * YC * M];  // [b][yc][x]  min over y-chunk
__device__ float g_col[BATCH * XT * M];  // [b][xt][y]  min over x-tile
__device__ float g_sums[NRED];           // per-reduce-block partial sums
__device__ unsigned int g_count;         // last-block-done counter (self-resets)

__global__ __launch_bounds__(TX) void chamfer_main(const float* __restrict__ x,
                                                   const float* __restrict__ y) {
    __shared__ float4 sy[YCHUNK];        // y chunk: (px,py,pz,|p|^2)
    __shared__ float scol[NW][YCHUNK];   // per-warp col-min partials

    int bid = blockIdx.x;
    int yc = bid & (YC - 1);
    int xt = (bid >> 5) & (XT - 1);
    int b  = bid >> 8;

    int tid = threadIdx.x;
    int lane = tid & 31;
    int w = tid >> 5;

    // cooperative load of the y chunk, precomputing |p|^2
    const float* ysrc = y + ((size_t)b * M + yc * YCHUNK) * 3;
    if (tid < YCHUNK) {
        float p0 = ysrc[tid * 3 + 0];
        float p1 = ysrc[tid * 3 + 1];
        float p2 = ysrc[tid * 3 + 2];
        sy[tid] = make_float4(p0, p1, p2, fmaf(p0, p0, fmaf(p1, p1, p2 * p2)));
    }
#pragma unroll
    for (int i = 0; i < NW; i++) ((float*)scol)[i * TX + tid] = FLT_MAX;

    // my R x-points -> registers
    float n0[R], n1[R], n2[R], sx[R], rmin[R];
    const float* xsrc = x + ((size_t)b * M + xt * XPB) * 3;
#pragma unroll
    for (int r = 0; r < R; r++) {
        int xi = tid + r * TX;
        float a0 = xsrc[xi * 3 + 0];
        float a1 = xsrc[xi * 3 + 1];
        float a2 = xsrc[xi * 3 + 2];
        sx[r] = fmaf(a0, a0, fmaf(a1, a1, a2 * a2));
        n0[r] = -2.0f * a0;
        n1[r] = -2.0f * a1;
        n2[r] = -2.0f * a2;
        rmin[r] = FLT_MAX;
    }
    __syncthreads();

    // volatile pins LDS/STS order so the cross-lane RMW on scol is safe:
    // lane-staggered j gives distinct addresses within each step; an address
    // is revisited one step later, after the prior STS (same warp, program
    // order through the LSU).
    volatile float* sc = scol[w];

#pragma unroll 4
    for (int k = 0; k < YCHUNK; k++) {
        int j = (k + lane) & (YCHUNK - 1);
        float4 p = sy[j];
        float d0 = sx[0] + fmaf(n0[0], p.x, fmaf(n1[0], p.y, fmaf(n2[0], p.z, p.w)));
        float d1 = sx[1] + fmaf(n0[1], p.x, fmaf(n1[1], p.y, fmaf(n2[1], p.z, p.w)));
        float d2 = sx[2] + fmaf(n0[2], p.x, fmaf(n1[2], p.y, fmaf(n2[2], p.z, p.w)));
        float d3 = sx[3] + fmaf(n0[3], p.x, fmaf(n1[3], p.y, fmaf(n2[3], p.z, p.w)));
        rmin[0] = fminf(rmin[0], d0);
        rmin[1] = fminf(rmin[1], d1);
        rmin[2] = fminf(rmin[2], d2);
        rmin[3] = fminf(rmin[3], d3);
        float c = fminf(fminf(d0, d1), fminf(d2, d3));
        sc[j] = fminf(sc[j], c);
    }

    // row-min partials (per x, min over this y-chunk)
#pragma unroll
    for (int r = 0; r < R; r++)
        g_row[((size_t)b * YC + yc) * M + xt * XPB + tid + r * TX] = rmin[r];

    __syncthreads();

    // merge per-warp col-mins, write col partials (per y, min over this x-tile)
    if (tid < YCHUNK) {
        float v = fminf(fminf(scol[0][tid], scol[1][tid]),
                        fminf(scol[2][tid], scol[3][tid]));
        g_col[((size_t)b * XT + xt) * M + yc * YCHUNK + tid] = v;
    }
}

// 64 blocks: [b][seg]; seg 0-7 reduce rows (min over YC), seg 8-15 cols
// (min over XT). Last block to finish folds g_sums into out (deterministic:
// fixed-order sum regardless of which block runs it).
__global__ __launch_bounds__(256) void chamfer_reduce(float* __restrict__ out) {
    int seg = blockIdx.x & 15;
    int b   = blockIdx.x >> 4;
    int tid = threadIdx.x;
    float sum = 0.0f;

    if (seg < 8) {
        const float* base = g_row + (size_t)b * YC * M + seg * 512;
#pragma unroll
        for (int r = 0; r < 2; r++) {
            const float* p = base + r * 256 + tid;
            float v = p[0];
#pragma unroll
            for (int c = 1; c < YC; c++) v = fminf(v, p[(size_t)c * M]);
            sum += sqrtf(fmaxf(v, 0.0f));
        }
    } else {
        const float* base = g_col + (size_t)b * XT * M + (seg - 8) * 512;
#pragma unroll
        for (int r = 0; r < 2; r++) {
            const float* p = base + r * 256 + tid;
            float v = p[0];
#pragma unroll
            for (int c = 1; c < XT; c++) v = fminf(v, p[(size_t)c * M]);
            sum += sqrtf(fmaxf(v, 0.0f));
        }
    }

    __shared__ float red[8];
    for (int o = 16; o; o >>= 1) sum += __shfl_down_sync(0xffffffffu, sum, o);
    if ((tid & 31) == 0) red[tid >> 5] = sum;
    __syncthreads();
    if (tid == 0) {
        float s = 0.0f;
#pragma unroll
        for (int i = 0; i < 8; i++) s += red[i];
        g_sums[blockIdx.x] = s;
        __threadfence();
        unsigned int n = atomicAdd(&g_count, 1u);
        if (n == NRED - 1) {
            __threadfence();
#pragma unroll
            for (int bb = 0; bb < BATCH; bb++) {
                float t = 0.0f;
#pragma unroll
                for (int i = 0; i < 16; i++) t += g_sums[bb * 16 + i];
                out[bb] = t * (1.0f / (float)M);
            }
            g_count = 0;  // reset for next graph replay
        }
    }
}

extern "C" void kernel_launch(void* const* d_in, const int* in_sizes, int n_in,
                              void* d_out, int out_size) {
    const float* x = (const float*)d_in[0];
    const float* y = (const float*)d_in[1];
    float* out = (float*)d_out;

    chamfer_main<<<NBLK, TX>>>(x, y);
    chamfer_reduce<<<NRED, 256>>>(out);
}

// round 8
// speedup vs baseline: 1.6819x; 1.1368x over previous
#include <cuda_runtime.h>
#include <cfloat>

#define BATCH 4
#define M 4096
#define TX 128
#define NW (TX / 32)            // 4 warps
#define R 4                     // x-points per thread
#define XPB (TX * R)            // 512 x per block
#define XT (M / XPB)            // 8 x-tiles
#define YC 32                   // y-chunks
#define YCHUNK (M / YC)         // 128 y per chunk
#define NBLK (BATCH * XT * YC)  // 1024 blocks
#define NRED 64                 // reduce blocks

// Order-preserving min-keys: key = ~float_bits(d^2), d^2 >= 0.
// Larger key == smaller d^2; all real keys > 0, so zero-init is the identity
// for atomicMax. chamfer_reduce resets entries to 0 after consuming them,
// so every graph replay starts from the identity state.
__device__ unsigned int g_rowkey[BATCH * M];  // [b][x]  min over all y
__device__ unsigned int g_colkey[BATCH * M];  // [b][y]  min over all x
__device__ float g_sums[NRED];
__device__ unsigned int g_count;              // self-resetting done counter

__global__ __launch_bounds__(TX) void chamfer_main(const float* __restrict__ x,
                                                   const float* __restrict__ y) {
    __shared__ float4 sy[2 * YCHUNK];        // y chunk doubled: linear index
    __shared__ float scol[NW][2 * YCHUNK];   // per-warp col-min, doubled

    int bid = blockIdx.x;
    int yc = bid & (YC - 1);
    int xt = (bid >> 5) & (XT - 1);
    int b  = bid >> 8;

    int tid = threadIdx.x;
    int lane = tid & 31;
    int w = tid >> 5;

    // load y chunk (duplicated so sy[lane+k] needs no mask), precompute |p|^2
    const float* ysrc = y + ((size_t)b * M + yc * YCHUNK) * 3;
    if (tid < YCHUNK) {
        float p0 = ysrc[tid * 3 + 0];
        float p1 = ysrc[tid * 3 + 1];
        float p2 = ysrc[tid * 3 + 2];
        float4 v = make_float4(p0, p1, p2, fmaf(p0, p0, fmaf(p1, p1, p2 * p2)));
        sy[tid] = v;
        sy[tid + YCHUNK] = v;
    }
#pragma unroll
    for (int i = 0; i < NW * 2 * YCHUNK / TX; i++)
        ((float*)scol)[i * TX + tid] = FLT_MAX;

    // my R x-points -> registers
    float n0[R], n1[R], n2[R], sx[R], rmin[R];
    const float* xsrc = x + ((size_t)b * M + xt * XPB) * 3;
#pragma unroll
    for (int r = 0; r < R; r++) {
        int xi = tid + r * TX;
        float a0 = xsrc[xi * 3 + 0];
        float a1 = xsrc[xi * 3 + 1];
        float a2 = xsrc[xi * 3 + 2];
        sx[r] = fmaf(a0, a0, fmaf(a1, a1, a2 * a2));
        n0[r] = -2.0f * a0;
        n1[r] = -2.0f * a1;
        n2[r] = -2.0f * a2;
        rmin[r] = FLT_MAX;
    }
    __syncthreads();

    // volatile pins LDS/STS order: lane-staggered linear index gives distinct
    // addresses within each step; an address written by lane l+1 at step k is
    // re-read by lane l at step k+1 — same warp, program order through LSU.
    volatile float* sc = scol[w] + lane;
    const float4* syp = sy + lane;

#pragma unroll 8
    for (int k = 0; k < YCHUNK; k++) {
        float4 p = syp[k];
        float d0 = sx[0] + fmaf(n0[0], p.x, fmaf(n1[0], p.y, fmaf(n2[0], p.z, p.w)));
        float d1 = sx[1] + fmaf(n0[1], p.x, fmaf(n1[1], p.y, fmaf(n2[1], p.z, p.w)));
        float d2 = sx[2] + fmaf(n0[2], p.x, fmaf(n1[2], p.y, fmaf(n2[2], p.z, p.w)));
        float d3 = sx[3] + fmaf(n0[3], p.x, fmaf(n1[3], p.y, fmaf(n2[3], p.z, p.w)));
        rmin[0] = fminf(rmin[0], d0);
        rmin[1] = fminf(rmin[1], d1);
        rmin[2] = fminf(rmin[2], d2);
        rmin[3] = fminf(rmin[3], d3);
        float c = fminf(fminf(d0, d1), fminf(d2, d3));
        sc[k] = fminf(sc[k], c);
    }

    // rows: fold via order-preserving atomicMax key
#pragma unroll
    for (int r = 0; r < R; r++) {
        unsigned int key = ~__float_as_uint(fmaxf(rmin[r], 0.0f));
        atomicMax(&g_rowkey[(size_t)b * M + xt * XPB + tid + r * TX], key);
    }

    __syncthreads();

    // merge doubled halves + warps, fold cols via atomicMax key
    if (tid < YCHUNK) {
        float v = FLT_MAX;
#pragma unroll
        for (int i = 0; i < NW; i++)
            v = fminf(v, fminf(scol[i][tid], scol[i][tid + YCHUNK]));
        unsigned int key = ~__float_as_uint(fmaxf(v, 0.0f));
        atomicMax(&g_colkey[(size_t)b * M + yc * YCHUNK + tid], key);
    }
}

// 64 blocks x 256 threads, 512 keys each: blocks 0-31 rows, 32-63 cols.
// Each block covers one contiguous segment of a single batch (512 | 4096).
// Keys are reset to 0 after reading (identity for next replay).
__global__ __launch_bounds__(256) void chamfer_reduce(float* __restrict__ out) {
    int blk = blockIdx.x;
    int tid = threadIdx.x;
    unsigned int* base = (blk < 32) ? (g_rowkey + blk * 512)
                                    : (g_colkey + (blk - 32) * 512);
    float sum = 0.0f;
#pragma unroll
    for (int r = 0; r < 2; r++) {
        unsigned int k = base[r * 256 + tid];
        base[r * 256 + tid] = 0u;
        sum += sqrtf(__uint_as_float(~k));
    }

    __shared__ float red[8];
    for (int o = 16; o; o >>= 1) sum += __shfl_down_sync(0xffffffffu, sum, o);
    if ((tid & 31) == 0) red[tid >> 5] = sum;
    __syncthreads();
    if (tid == 0) {
        float s = 0.0f;
#pragma unroll
        for (int i = 0; i < 8; i++) s += red[i];
        g_sums[blk] = s;
        __threadfence();
        unsigned int n = atomicAdd(&g_count, 1u);
        if (n == NRED - 1) {
            __threadfence();
#pragma unroll
            for (int bb = 0; bb < BATCH; bb++) {
                float t = 0.0f;
#pragma unroll
                for (int i = 0; i < 8; i++)
                    t += g_sums[bb * 8 + i] + g_sums[32 + bb * 8 + i];
                out[bb] = t * (1.0f / (float)M);
            }
            g_count = 0;  // reset for next graph replay
        }
    }
}

extern "C" void kernel_launch(void* const* d_in, const int* in_sizes, int n_in,
                              void* d_out, int out_size) {
    const float* x = (const float*)d_in[0];
    const float* y = (const float*)d_in[1];
    float* out = (float*)d_out;

    chamfer_main<<<NBLK, TX>>>(x, y);
    chamfer_reduce<<<NRED, 256>>>(out);
}